// round 1
// baseline (speedup 1.0000x reference)
#include <cuda_runtime.h>
#include <cstdint>

#define FULL_MASK 0xFFFFFFFFu

static constexpr float EPS = 1e-10f;
static constexpr float FAR_DELTA = 1e10f;
static constexpr int P = 128;           // samples per ray
static constexpr int C = 3;             // channels
static constexpr int CHUNKS = P / 32;   // 4

// One warp per ray. Warp-scan exclusive cumprod for transmittance.
__global__ __launch_bounds__(256) void volume_render_kernel(
    const float* __restrict__ density,       // [N, P]
    const float* __restrict__ feature,       // [N, P, 3]
    const float* __restrict__ depth_values,  // [N, P]
    float* __restrict__ out,                 // [N*3 feat | N depth]
    int N)
{
    const int warp_in_block = threadIdx.x >> 5;
    const int lane = threadIdx.x & 31;
    const int ray = blockIdx.x * (blockDim.x >> 5) + warp_in_block;
    if (ray >= N) return;

    const size_t base = (size_t)ray * P;
    const float* dens_row  = density      + base;
    const float* depth_row = depth_values + base;
    const float* feat_row  = feature      + base * C;

    float T = 1.0f;           // running transmittance across chunks
    float acc_r = 0.0f, acc_g = 0.0f, acc_b = 0.0f, acc_d = 0.0f;

    #pragma unroll
    for (int ch = 0; ch < CHUNKS; ++ch) {
        const int p = ch * 32 + lane;

        // coalesced loads
        const float d   = dens_row[p];
        const float z   = depth_row[p];

        // next depth: shuffle from lane+1; lane 31 loads one extra element
        float z_next = __shfl_down_sync(FULL_MASK, z, 1);
        if (lane == 31 && p + 1 < P) z_next = depth_row[p + 1];

        const float delta = (p == P - 1) ? FAR_DELTA : (z_next - z);
        const float relu_d = d > 0.0f ? d : 0.0f;
        const float one_minus_alpha = __expf(-relu_d * delta);  // = 1 - alpha
        const float alpha = 1.0f - one_minus_alpha;
        const float f = one_minus_alpha + EPS;                  // cumprod factor

        // warp inclusive product scan of f
        float v = f;
        #pragma unroll
        for (int off = 1; off < 32; off <<= 1) {
            const float t = __shfl_up_sync(FULL_MASK, v, off);
            if (lane >= off) v *= t;
        }
        // exclusive scan = inclusive shifted by one; lane 0 gets 1
        float excl = __shfl_up_sync(FULL_MASK, v, 1);
        if (lane == 0) excl = 1.0f;

        const float w = alpha * T * excl;   // weight for sample p

        // feature accumulate (3 floats, stride-12 but L1-friendly)
        const float* fp = feat_row + (size_t)p * C;
        acc_r += w * fp[0];
        acc_g += w * fp[1];
        acc_b += w * fp[2];
        acc_d += w * z;

        // carry transmittance: full-chunk product lives in lane 31's inclusive
        T *= __shfl_sync(FULL_MASK, v, 31);
    }

    // warp reduction of the four accumulators
    #pragma unroll
    for (int off = 16; off > 0; off >>= 1) {
        acc_r += __shfl_xor_sync(FULL_MASK, acc_r, off);
        acc_g += __shfl_xor_sync(FULL_MASK, acc_g, off);
        acc_b += __shfl_xor_sync(FULL_MASK, acc_b, off);
        acc_d += __shfl_xor_sync(FULL_MASK, acc_d, off);
    }

    if (lane == 0) {
        float* feat_out  = out;               // [N, 3]
        float* depth_out = out + (size_t)N * C; // [N]
        feat_out[(size_t)ray * C + 0] = acc_r;
        feat_out[(size_t)ray * C + 1] = acc_g;
        feat_out[(size_t)ray * C + 2] = acc_b;
        depth_out[ray] = acc_d;
    }
}

extern "C" void kernel_launch(void* const* d_in, const int* in_sizes, int n_in,
                              void* d_out, int out_size)
{
    const float* density      = (const float*)d_in[0];
    const float* feature      = (const float*)d_in[1];
    const float* depth_values = (const float*)d_in[2];
    float* out = (float*)d_out;

    const int N = in_sizes[0] / P;   // density is [N, P]

    const int warps_per_block = 8;   // 256 threads
    const int blocks = (N + warps_per_block - 1) / warps_per_block;
    volume_render_kernel<<<blocks, 256>>>(density, feature, depth_values, out, N);
}